// round 14
// baseline (speedup 1.0000x reference)
#include <cuda_runtime.h>
#include <cstdint>

#define XS    128
#define BATCH 8
#define MPTS  500000
#define NQUART  (BATCH * XS * 4)             // 4096 quarter-planes
#define GRID_ELEMS (BATCH * XS * XS * XS)    // 64 MiB
#define TPB_SCAT (MPTS / 8)                  // 62,500 scatter threads / batch

// Scratch (device globals: zero-initialized at load; g_done self-resets)
__device__ float g_grid[GRID_ELEMS];
__device__ int   g_done[NQUART];

// ---- L2 evict-last cache-policy helpers ----
__device__ __forceinline__ uint64_t mk_evict_last() {
    uint64_t pol;
    asm("createpolicy.fractional.L2::evict_last.b64 %0, 1.0;" : "=l"(pol));
    return pol;
}
__device__ __forceinline__ void red_add_el(float* p, float v, uint64_t pol) {
    asm volatile("red.global.L2::cache_hint.add.f32 [%0], %1, %2;"
                 :: "l"(p), "f"(v), "l"(pol) : "memory");
}
__device__ __forceinline__ float4 ldg4_el(const float4* p, uint64_t pol) {
    float4 r;
    asm volatile("ld.global.L2::cache_hint.v4.f32 {%0,%1,%2,%3}, [%4], %5;"
                 : "=f"(r.x), "=f"(r.y), "=f"(r.z), "=f"(r.w)
                 : "l"(p), "l"(pol) : "memory");
    return r;
}
__device__ __forceinline__ void stg4_el(float4* p, float4 v, uint64_t pol) {
    asm volatile("st.global.L2::cache_hint.v4.f32 [%0], {%1,%2,%3,%4}, %5;"
                 :: "l"(p), "f"(v.x), "f"(v.y), "f"(v.z), "f"(v.w), "l"(pol)
                 : "memory");
}

// ---------------------------------------------------------------------------
// Kernel 1: scatter-add (R13 form, proven ~29 us). 8 points/thread, __ldcs
// input, evict-last REDs, 32-bit offsets. Block 0 zeroes d_out.
// ---------------------------------------------------------------------------
__global__ void __launch_bounds__(256) scatter_kernel(
        const int4*   __restrict__ idx4,
        const float4* __restrict__ val4,
        float*        __restrict__ d_out) {
    if (blockIdx.x == 0 && threadIdx.x < 2 * BATCH) d_out[threadIdx.x] = 0.f;

    const int nthreads = BATCH * TPB_SCAT;          // 500,000
    int tid = blockIdx.x * blockDim.x + threadIdx.x;
    if (tid >= nthreads) return;

    const uint64_t pol = mk_evict_last();

    int b = tid / TPB_SCAT;
    int t = tid - b * TPB_SCAT;
    unsigned base = (unsigned)b << 21;
    long p0 = (long)b * MPTS + (long)t * 8;

    int4 a[6];
    #pragma unroll
    for (int s = 0; s < 6; s++) a[s] = __ldcs(&idx4[(p0 * 3) / 4 + s]);
    float4 v0 = __ldcs(&val4[p0 / 4 + 0]);
    float4 v1 = __ldcs(&val4[p0 / 4 + 1]);
    const int* ai = (const int*)a;
    float vals[8] = { v0.x, v0.y, v0.z, v0.w, v1.x, v1.y, v1.z, v1.w };

    #pragma unroll
    for (int s = 0; s < 8; s++) {
        unsigned off = base + ((unsigned)ai[3 * s] << 14)
                     + ((unsigned)ai[3 * s + 1] << 7) + (unsigned)ai[3 * s + 2];
        red_add_el(&g_grid[off], vals[s], pol);
    }
}

// ---------------------------------------------------------------------------
__device__ __forceinline__ void diff4(const float4& a, const float4& b,
                                      float& tv, float& mse) {
    float d0 = b.x - a.x, d1 = b.y - a.y, d2 = b.z - a.z, d3 = b.w - a.w;
    tv  += fabsf(d0) + fabsf(d1) + fabsf(d2) + fabsf(d3);
    mse += d0 * d0 + d1 * d1 + d2 * d2 + d3 * d3;
}
__device__ __forceinline__ void kdiffs(const float4& c, bool cross,
                                       float& tv, float& mse) {
    float d0 = c.y - c.x, d1 = c.z - c.y, d2 = c.w - c.z;
    tv  += fabsf(d0) + fabsf(d1) + fabsf(d2);
    mse += d0 * d0 + d1 * d1 + d2 * d2;
    float nx = __shfl_down_sync(0xffffffffu, c.x, 1);
    if (cross) { float d3 = nx - c.w; tv += fabsf(d3); mse += d3 * d3; }
}
__device__ __forceinline__ void plane_kj(const float4 c[4], const float4& jb,
                                         bool has_jb, bool crossk,
                                         float& tv, float& mse) {
    #pragma unroll
    for (int r = 0; r < 4; r++) kdiffs(c[r], crossk, tv, mse);
    diff4(c[0], c[1], tv, mse);
    diff4(c[1], c[2], tv, mse);
    diff4(c[2], c[3], tv, mse);
    if (has_jb) diff4(c[3], jb, tv, mse);
}
__device__ __forceinline__ void zero_quarter(int qidx, int tid, uint64_t pol) {
    float4* gw = (float4*)g_grid;
    const long qb = (long)qidx << 10;
    const float4 z = make_float4(0.f, 0.f, 0.f, 0.f);
    #pragma unroll
    for (int it = 0; it < 4; ++it)
        stg4_el(&gw[qb + it * 256 + tid], z, pol);
    if (tid == 0) g_done[qidx] = 0;
}

// ---------------------------------------------------------------------------
// Kernel 2: TV+MSE reduce + re-zero, i-chained 4-plane chunks (1024 blocks).
// 24 LDG.128 per thread per 4 planes (6/plane vs 7/plane for plane-pairs).
// Quarter-granular zero protocol in chunk form (R9-verified targets).
// ---------------------------------------------------------------------------
__global__ void __launch_bounds__(256, 5) reduce_zero_kernel(float* __restrict__ d_out) {
    const int rb    = blockIdx.x;                  // 0..1023
    const int b     = rb >> 7;
    const int local = rb & 127;
    const int ic    = local >> 2;                  // i-chunk 0..31
    const int q     = local & 3;                   // quarter (j-strip of 32)
    const int p0    = b * XS + ic * 4;             // first owned plane
    const int lane  = threadIdx.x & 31;
    const int wg    = threadIdx.x >> 5;
    const int jrow0 = q * 32 + wg * 4;
    const bool has_jb = (jrow0 + 4) < XS;
    const bool crossk = (lane != 31);
    const float4* __restrict__ g4 = (const float4*)g_grid;

    const uint64_t pol = mk_evict_last();
    const long pb = (long)p0 << 12;
    const int  fo = jrow0 * 32 + lane;
    const float4 z = make_float4(0.f, 0.f, 0.f, 0.f);

    float tv = 0.f, mse = 0.f;
    float4 c[4], n[4];

    // plane p0
    #pragma unroll
    for (int r = 0; r < 4; r++) c[r] = ldg4_el(&g4[pb + fo + r * 32], pol);
    {
        float4 jb = has_jb ? ldg4_el(&g4[pb + fo + 128], pol) : z;
        plane_kj(c, jb, has_jb, crossk, tv, mse);
    }
    // planes p0+1..p0+3 with register carry
    #pragma unroll
    for (int t = 1; t < 4; ++t) {
        const long pbt = pb + (long)t * 4096;
        #pragma unroll
        for (int r = 0; r < 4; r++) n[r] = ldg4_el(&g4[pbt + fo + r * 32], pol);
        float4 jb = has_jb ? ldg4_el(&g4[pbt + fo + 128], pol) : z;
        #pragma unroll
        for (int r = 0; r < 4; r++) diff4(c[r], n[r], tv, mse);
        plane_kj(n, jb, has_jb, crossk, tv, mse);
        #pragma unroll
        for (int r = 0; r < 4; r++) c[r] = n[r];
    }
    // seam plane p0+4
    if (ic < 31) {
        const long pbs = pb + 4L * 4096;
        #pragma unroll
        for (int r = 0; r < 4; r++) {
            float4 e = ldg4_el(&g4[pbs + fo + r * 32], pol);
            diff4(c[r], e, tv, mse);
        }
    }

    // block reduce -> 2 atomics into d_out
    #pragma unroll
    for (int off = 16; off > 0; off >>= 1) {
        tv  += __shfl_down_sync(0xffffffffu, tv,  off);
        mse += __shfl_down_sync(0xffffffffu, mse, off);
    }
    __shared__ float stv[8], smse[8];
    if (lane == 0) { stv[wg] = tv; smse[wg] = mse; }
    __syncthreads();
    if (threadIdx.x == 0) {
        float ttv = 0.f, tmse = 0.f;
        #pragma unroll
        for (int s = 0; s < 8; s++) { ttv += stv[s]; tmse += smse[s]; }
        const float tv_norm  = 1.f / (float)(XS * XS * XS);
        const float mse_norm = 1.f / (float)(2 * XS * XS - 2 * XS);
        atomicAdd(&d_out[b],         ttv  * tv_norm);
        atomicAdd(&d_out[BATCH + b], tmse * mse_norm);
    }

    // ---- quarter-granular zero protocol (chunk form, R9-verified) ----
    __shared__ int zmask;
    if (threadIdx.x == 0) zmask = 0;
    __syncthreads();                                // all grid reads retired
    if (threadIdx.x == 0) {
        __threadfence();
        int m = 0;
        #pragma unroll
        for (int t = 0; t < 4; ++t) {               // own quarters
            int tgt = 1 + (q > 0 ? 1 : 0) + ((t == 0 && ic > 0) ? 1 : 0);
            if (atomicAdd(&g_done[((p0 + t) << 2) + q], 1) + 1 == tgt)
                m |= 1 << t;
        }
        if (q < 3) {                                // j-next quarters
            #pragma unroll
            for (int t = 0; t < 4; ++t) {
                int tgt = 2 + ((t == 0 && ic > 0) ? 1 : 0);
                if (atomicAdd(&g_done[((p0 + t) << 2) + q + 1], 1) + 1 == tgt)
                    m |= 1 << (4 + t);
            }
        }
        if (ic < 31) {                              // seam quarter
            int tgt = 2 + (q > 0 ? 1 : 0);
            if (atomicAdd(&g_done[((p0 + 4) << 2) + q], 1) + 1 == tgt)
                m |= 1 << 8;
        }
        zmask = m;
    }
    __syncthreads();
    int m = zmask;
    #pragma unroll
    for (int t = 0; t < 4; ++t)
        if (m & (1 << t))       zero_quarter(((p0 + t) << 2) + q,     threadIdx.x, pol);
    #pragma unroll
    for (int t = 0; t < 4; ++t)
        if (m & (1 << (4 + t))) zero_quarter(((p0 + t) << 2) + q + 1, threadIdx.x, pol);
    if (m & (1 << 8))           zero_quarter(((p0 + 4) << 2) + q,     threadIdx.x, pol);
}

// ---------------------------------------------------------------------------
extern "C" void kernel_launch(void* const* d_in, const int* in_sizes, int n_in,
                              void* d_out, int out_size) {
    const int*   indices = (const int*)d_in[0];    // (B, M, 3) int32
    const float* values  = (const float*)d_in[1];  // (B, M) float32
    float* out = (float*)d_out;                    // (2, B) float32

    {
        int nthreads = BATCH * TPB_SCAT;            // 500,000
        int threads = 256;
        int blocks = (nthreads + threads - 1) / threads;
        scatter_kernel<<<blocks, threads>>>((const int4*)indices,
                                            (const float4*)values, out);
    }
    {
        reduce_zero_kernel<<<1024, 256>>>(out);
    }
}

// round 15
// speedup vs baseline: 1.0235x; 1.0235x over previous
#include <cuda_runtime.h>
#include <cstdint>

#define XS    128
#define BATCH 8
#define MPTS  500000
#define NQUART  (BATCH * XS * 4)             // 4096 quarter-planes
#define GRID_ELEMS (BATCH * XS * XS * XS)    // 64 MiB
#define TPB_SCAT (MPTS / 8)                  // 62,500 scatter threads / batch

// Scratch (device globals: zero-initialized at load; g_done self-resets)
__device__ float g_grid[GRID_ELEMS];
__device__ int   g_done[NQUART];

// ---- L2 evict-last cache-policy helpers ----
__device__ __forceinline__ uint64_t mk_evict_last() {
    uint64_t pol;
    asm("createpolicy.fractional.L2::evict_last.b64 %0, 1.0;" : "=l"(pol));
    return pol;
}
__device__ __forceinline__ void red_add_el(float* p, float v, uint64_t pol) {
    asm volatile("red.global.L2::cache_hint.add.f32 [%0], %1, %2;"
                 :: "l"(p), "f"(v), "l"(pol) : "memory");
}
__device__ __forceinline__ float4 ldg4_el(const float4* p, uint64_t pol) {
    float4 r;
    asm volatile("ld.global.L2::cache_hint.v4.f32 {%0,%1,%2,%3}, [%4], %5;"
                 : "=f"(r.x), "=f"(r.y), "=f"(r.z), "=f"(r.w)
                 : "l"(p), "l"(pol) : "memory");
    return r;
}
__device__ __forceinline__ void stg4_el(float4* p, float4 v, uint64_t pol) {
    asm volatile("st.global.L2::cache_hint.v4.f32 [%0], {%1,%2,%3,%4}, %5;"
                 :: "l"(p), "f"(v.x), "f"(v.y), "f"(v.z), "f"(v.w), "l"(pol)
                 : "memory");
}

// ---------------------------------------------------------------------------
// Kernel 1: scatter-add (R13 form, proven ~29 us — L1tex-wavefront floor).
// ---------------------------------------------------------------------------
__global__ void __launch_bounds__(256) scatter_kernel(
        const int4*   __restrict__ idx4,
        const float4* __restrict__ val4,
        float*        __restrict__ d_out) {
    if (blockIdx.x == 0 && threadIdx.x < 2 * BATCH) d_out[threadIdx.x] = 0.f;

    const int nthreads = BATCH * TPB_SCAT;          // 500,000
    int tid = blockIdx.x * blockDim.x + threadIdx.x;
    if (tid >= nthreads) return;

    const uint64_t pol = mk_evict_last();

    int b = tid / TPB_SCAT;
    int t = tid - b * TPB_SCAT;
    unsigned base = (unsigned)b << 21;
    long p0 = (long)b * MPTS + (long)t * 8;

    int4 a[6];
    #pragma unroll
    for (int s = 0; s < 6; s++) a[s] = __ldcs(&idx4[(p0 * 3) / 4 + s]);
    float4 v0 = __ldcs(&val4[p0 / 4 + 0]);
    float4 v1 = __ldcs(&val4[p0 / 4 + 1]);
    const int* ai = (const int*)a;
    float vals[8] = { v0.x, v0.y, v0.z, v0.w, v1.x, v1.y, v1.z, v1.w };

    #pragma unroll
    for (int s = 0; s < 8; s++) {
        unsigned off = base + ((unsigned)ai[3 * s] << 14)
                     + ((unsigned)ai[3 * s + 1] << 7) + (unsigned)ai[3 * s + 2];
        red_add_el(&g_grid[off], vals[s], pol);
    }
}

// ---------------------------------------------------------------------------
__device__ __forceinline__ void diff4(const float4& a, const float4& b,
                                      float& tv, float& mse) {
    float d0 = b.x - a.x, d1 = b.y - a.y, d2 = b.z - a.z, d3 = b.w - a.w;
    tv  += fabsf(d0) + fabsf(d1) + fabsf(d2) + fabsf(d3);
    mse += d0 * d0 + d1 * d1 + d2 * d2 + d3 * d3;
}
__device__ __forceinline__ void kdiffs(const float4& c, bool cross,
                                       float& tv, float& mse) {
    float d0 = c.y - c.x, d1 = c.z - c.y, d2 = c.w - c.z;
    tv  += fabsf(d0) + fabsf(d1) + fabsf(d2);
    mse += d0 * d0 + d1 * d1 + d2 * d2;
    float nx = __shfl_down_sync(0xffffffffu, c.x, 1);
    if (cross) { float d3 = nx - c.w; tv += fabsf(d3); mse += d3 * d3; }
}
__device__ __forceinline__ void plane_kj(const float4 c[4], const float4& jb,
                                         bool has_jb, bool crossk,
                                         float& tv, float& mse) {
    #pragma unroll
    for (int r = 0; r < 4; r++) kdiffs(c[r], crossk, tv, mse);
    diff4(c[0], c[1], tv, mse);
    diff4(c[1], c[2], tv, mse);
    diff4(c[2], c[3], tv, mse);
    if (has_jb) diff4(c[3], jb, tv, mse);
}
__device__ __forceinline__ void zero_quarter(int qidx, int tid, uint64_t pol) {
    float4* gw = (float4*)g_grid;
    const long qb = (long)qidx << 10;
    const float4 z = make_float4(0.f, 0.f, 0.f, 0.f);
    #pragma unroll
    for (int it = 0; it < 4; ++it)
        stg4_el(&gw[qb + it * 256 + tid], z, pol);
    if (tid == 0) g_done[qidx] = 0;
}

// ---------------------------------------------------------------------------
// Kernel 2: TV+MSE reduce + re-zero, plane-pair blocks (2048, R13 form) with
// SMEM j-boundary exchange: warp wg's j-boundary row == warp wg+1's row 0,
// so exchange c[0]/n[0] through smem and drop 2 LDGs for 7/8 of threads.
// ---------------------------------------------------------------------------
__global__ void __launch_bounds__(256, 4) reduce_zero_kernel(float* __restrict__ d_out) {
    const int group = blockIdx.x >> 2;             // 0..511
    const int q     = blockIdx.x & 3;
    const int p0    = group * 2;                   // even global plane
    const int b     = p0 >> 7;
    const int i0    = p0 & 127;
    const int lane  = threadIdx.x & 31;
    const int wg    = threadIdx.x >> 5;
    const int jrow0 = q * 32 + wg * 4;
    const bool has_jb = (jrow0 + 4) < XS;          // false only q==3 && wg==7
    const bool crossk = (lane != 31);
    const float4* __restrict__ g4 = (const float4*)g_grid;

    const uint64_t pol = mk_evict_last();

    const long pb0 = (long)p0 << 12;
    const long pb1 = pb0 + 4096;
    const int  fo  = jrow0 * 32 + lane;
    const float4 z = make_float4(0.f, 0.f, 0.f, 0.f);

    float tv = 0.f, mse = 0.f;
    float4 c[4], n[4], jb0, jb1;

    // ---- load phase: 8 center LDG.128 (front-batched, evict-last) ----
    #pragma unroll
    for (int r = 0; r < 4; r++) c[r] = ldg4_el(&g4[pb0 + fo + r * 32], pol);
    #pragma unroll
    for (int r = 0; r < 4; r++) n[r] = ldg4_el(&g4[pb1 + fo + r * 32], pol);

    // ---- j-boundary exchange through smem (row jrow0+4 == wg+1's row 0) ----
    __shared__ float4 srow[2][8][32];
    srow[0][wg][lane] = c[0];
    srow[1][wg][lane] = n[0];
    __syncthreads();
    if (wg < 7) {
        jb0 = srow[0][wg + 1][lane];
        jb1 = srow[1][wg + 1][lane];
    } else if (has_jb) {                            // wg==7, q<3: next quarter
        jb0 = ldg4_el(&g4[pb0 + fo + 128], pol);
        jb1 = ldg4_el(&g4[pb1 + fo + 128], pol);
    } else {
        jb0 = z; jb1 = z;
    }

    // ---- compute p0 + i-diffs; recycle c[] for the ext plane ----
    plane_kj(c, jb0, has_jb, crossk, tv, mse);
    #pragma unroll
    for (int r = 0; r < 4; r++) diff4(c[r], n[r], tv, mse);

    const bool has_ext = (i0 < XS - 2);
    if (has_ext) {
        const long pb2 = pb1 + 4096;
        #pragma unroll
        for (int r = 0; r < 4; r++) c[r] = ldg4_el(&g4[pb2 + fo + r * 32], pol);
    }
    plane_kj(n, jb1, has_jb, crossk, tv, mse);
    if (has_ext) {
        #pragma unroll
        for (int r = 0; r < 4; r++) diff4(n[r], c[r], tv, mse);
    }

    // ---- block reduce -> 2 atomics into d_out ----
    #pragma unroll
    for (int off = 16; off > 0; off >>= 1) {
        tv  += __shfl_down_sync(0xffffffffu, tv,  off);
        mse += __shfl_down_sync(0xffffffffu, mse, off);
    }
    __shared__ float stv[8], smse[8];
    if (lane == 0) { stv[wg] = tv; smse[wg] = mse; }
    __syncthreads();
    if (threadIdx.x == 0) {
        float ttv = 0.f, tmse = 0.f;
        #pragma unroll
        for (int s = 0; s < 8; s++) { ttv += stv[s]; tmse += smse[s]; }
        const float tv_norm  = 1.f / (float)(XS * XS * XS);
        const float mse_norm = 1.f / (float)(2 * XS * XS - 2 * XS);
        atomicAdd(&d_out[b],         ttv  * tv_norm);
        atomicAdd(&d_out[BATCH + b], tmse * mse_norm);
    }

    // ---- quarter-granular zero protocol (R7/R13 form, proven) ----
    __shared__ int zmask;
    if (threadIdx.x == 0) zmask = 0;
    __syncthreads();                                // all grid reads retired
    if (threadIdx.x == 0) {
        __threadfence();
        int m = 0;
        int q0 = (p0 << 2) + q;
        int q1 = ((p0 + 1) << 2) + q;
        int tgt0 = 1 + (q > 0 ? 1 : 0) + (i0 > 0 ? 1 : 0);
        int tgt1 = 1 + (q > 0 ? 1 : 0);
        if (atomicAdd(&g_done[q0], 1) + 1 == tgt0) m |= 1;
        if (atomicAdd(&g_done[q1], 1) + 1 == tgt1) m |= 2;
        if (q < 3) {
            int j0 = (p0 << 2) + q + 1;
            int j1 = ((p0 + 1) << 2) + q + 1;
            if (atomicAdd(&g_done[j0], 1) + 1 == 2 + (i0 > 0 ? 1 : 0)) m |= 4;
            if (atomicAdd(&g_done[j1], 1) + 1 == 2) m |= 8;
        }
        if (has_ext) {
            int e0 = ((p0 + 2) << 2) + q;
            if (atomicAdd(&g_done[e0], 1) + 1 == 2 + (q > 0 ? 1 : 0)) m |= 16;
        }
        zmask = m;
    }
    __syncthreads();
    int m = zmask;
    if (m & 1)  zero_quarter((p0 << 2) + q,           threadIdx.x, pol);
    if (m & 2)  zero_quarter(((p0 + 1) << 2) + q,     threadIdx.x, pol);
    if (m & 4)  zero_quarter((p0 << 2) + q + 1,       threadIdx.x, pol);
    if (m & 8)  zero_quarter(((p0 + 1) << 2) + q + 1, threadIdx.x, pol);
    if (m & 16) zero_quarter(((p0 + 2) << 2) + q,     threadIdx.x, pol);
}

// ---------------------------------------------------------------------------
extern "C" void kernel_launch(void* const* d_in, const int* in_sizes, int n_in,
                              void* d_out, int out_size) {
    const int*   indices = (const int*)d_in[0];    // (B, M, 3) int32
    const float* values  = (const float*)d_in[1];  // (B, M) float32
    float* out = (float*)d_out;                    // (2, B) float32

    {
        int nthreads = BATCH * TPB_SCAT;            // 500,000
        int threads = 256;
        int blocks = (nthreads + threads - 1) / threads;
        scatter_kernel<<<blocks, threads>>>((const int4*)indices,
                                            (const float4*)values, out);
    }
    {
        reduce_zero_kernel<<<2048, 256>>>(out);
    }
}

// round 16
// speedup vs baseline: 1.0241x; 1.0006x over previous
#include <cuda_runtime.h>
#include <cstdint>

#define XS    128
#define BATCH 8
#define MPTS  500000
#define NUNIT (BATCH * XS * 8)               // 8192 (plane, strip) zero units
#define GRID_ELEMS (BATCH * XS * XS * XS)    // 64 MiB
#define TPB_SCAT (MPTS / 8)                  // 62,500 scatter threads / batch

// Scratch (device globals: zero-initialized at load; g_done self-resets)
__device__ float g_grid[GRID_ELEMS];
__device__ int   g_done[NUNIT];

// ---- L2 evict-last cache-policy helpers ----
__device__ __forceinline__ uint64_t mk_evict_last() {
    uint64_t pol;
    asm("createpolicy.fractional.L2::evict_last.b64 %0, 1.0;" : "=l"(pol));
    return pol;
}
__device__ __forceinline__ void red_add_el(float* p, float v, uint64_t pol) {
    asm volatile("red.global.L2::cache_hint.add.f32 [%0], %1, %2;"
                 :: "l"(p), "f"(v), "l"(pol) : "memory");
}
__device__ __forceinline__ float4 ldg4_el(const float4* p, uint64_t pol) {
    float4 r;
    asm volatile("ld.global.L2::cache_hint.v4.f32 {%0,%1,%2,%3}, [%4], %5;"
                 : "=f"(r.x), "=f"(r.y), "=f"(r.z), "=f"(r.w)
                 : "l"(p), "l"(pol) : "memory");
    return r;
}
__device__ __forceinline__ void stg4_el(float4* p, float4 v, uint64_t pol) {
    asm volatile("st.global.L2::cache_hint.v4.f32 [%0], {%1,%2,%3,%4}, %5;"
                 :: "l"(p), "f"(v.x), "f"(v.y), "f"(v.z), "f"(v.w), "l"(pol)
                 : "memory");
}

// ---------------------------------------------------------------------------
// Kernel 1: scatter-add (R13 form, proven — L1tex-wavefront/RED floor).
// ---------------------------------------------------------------------------
__global__ void __launch_bounds__(256) scatter_kernel(
        const int4*   __restrict__ idx4,
        const float4* __restrict__ val4,
        float*        __restrict__ d_out) {
    if (blockIdx.x == 0 && threadIdx.x < 2 * BATCH) d_out[threadIdx.x] = 0.f;

    const int nthreads = BATCH * TPB_SCAT;          // 500,000
    int tid = blockIdx.x * blockDim.x + threadIdx.x;
    if (tid >= nthreads) return;

    const uint64_t pol = mk_evict_last();

    int b = tid / TPB_SCAT;
    int t = tid - b * TPB_SCAT;
    unsigned base = (unsigned)b << 21;
    long p0 = (long)b * MPTS + (long)t * 8;

    int4 a[6];
    #pragma unroll
    for (int s = 0; s < 6; s++) a[s] = __ldcs(&idx4[(p0 * 3) / 4 + s]);
    float4 v0 = __ldcs(&val4[p0 / 4 + 0]);
    float4 v1 = __ldcs(&val4[p0 / 4 + 1]);
    const int* ai = (const int*)a;
    float vals[8] = { v0.x, v0.y, v0.z, v0.w, v1.x, v1.y, v1.z, v1.w };

    #pragma unroll
    for (int s = 0; s < 8; s++) {
        unsigned off = base + ((unsigned)ai[3 * s] << 14)
                     + ((unsigned)ai[3 * s + 1] << 7) + (unsigned)ai[3 * s + 2];
        red_add_el(&g_grid[off], vals[s], pol);
    }
}

// ---------------------------------------------------------------------------
__device__ __forceinline__ void diff4(const float4& a, const float4& b,
                                      float& tv, float& mse) {
    float d0 = b.x - a.x, d1 = b.y - a.y, d2 = b.z - a.z, d3 = b.w - a.w;
    tv  += fabsf(d0) + fabsf(d1) + fabsf(d2) + fabsf(d3);
    mse += d0 * d0 + d1 * d1 + d2 * d2 + d3 * d3;
}
__device__ __forceinline__ void kdiffs(const float4& c, bool cross,
                                       float& tv, float& mse) {
    float d0 = c.y - c.x, d1 = c.z - c.y, d2 = c.w - c.z;
    tv  += fabsf(d0) + fabsf(d1) + fabsf(d2);
    mse += d0 * d0 + d1 * d1 + d2 * d2;
    float nx = __shfl_down_sync(0xffffffffu, c.x, 1);
    if (cross) { float d3 = nx - c.w; tv += fabsf(d3); mse += d3 * d3; }
}
// zero one (plane, strip) unit: 16 rows x 32 float4 = 512 float4
__device__ __forceinline__ void zero_unit(int p, int s, int tid, uint64_t pol) {
    float4* gw = (float4*)g_grid;
    const long ub = (long)p * 4096 + s * 512;
    const float4 z = make_float4(0.f, 0.f, 0.f, 0.f);
    stg4_el(&gw[ub + tid], z, pol);
    stg4_el(&gw[ub + 256 + tid], z, pol);
    if (tid == 0) g_done[p * 8 + s] = 0;
}

// ---------------------------------------------------------------------------
// Kernel 2: TV+MSE reduce + re-zero. Block = (batch, 4-plane chunk, 16-row
// j-strip) -> 2048 blocks. Thread owns 2 rows/plane, register-carried across
// the chunk (i-diffs), j-boundary row is a same-block L1-hit LDG. Ext re-read
// traffic halves vs plane-pairs (16MB vs 32MB).
// ---------------------------------------------------------------------------
__global__ void __launch_bounds__(256, 5) reduce_zero_kernel(float* __restrict__ d_out) {
    const int rb    = blockIdx.x;                  // 0..2047
    const int b     = rb >> 8;
    const int local = rb & 255;
    const int ic    = local >> 3;                  // i-chunk 0..31
    const int s     = local & 7;                   // j-strip 0..7 (16 rows)
    const int p0    = b * XS + ic * 4;             // first owned plane
    const int lane  = threadIdx.x & 31;
    const int jg    = threadIdx.x >> 5;            // jgroup 0..7 (2 rows)
    const int jrow0 = s * 16 + jg * 2;
    const bool has_jb = !(s == 7 && jg == 7);      // row jrow0+2 exists?
    const bool crossk = (lane != 31);
    const float4* __restrict__ g4 = (const float4*)g_grid;

    const uint64_t pol = mk_evict_last();
    const long pb = (long)p0 << 12;
    const int  fo = jrow0 * 32 + lane;
    const float4 z = make_float4(0.f, 0.f, 0.f, 0.f);

    float tv = 0.f, mse = 0.f;
    float4 c0, c1, jb;

    // plane p0
    c0 = ldg4_el(&g4[pb + fo], pol);
    c1 = ldg4_el(&g4[pb + fo + 32], pol);
    jb = has_jb ? ldg4_el(&g4[pb + fo + 64], pol) : z;
    kdiffs(c0, crossk, tv, mse);
    kdiffs(c1, crossk, tv, mse);
    diff4(c0, c1, tv, mse);
    if (has_jb) diff4(c1, jb, tv, mse);

    // planes p0+1..p0+3: i-diffs via register carry, then own k/j
    #pragma unroll
    for (int t = 1; t < 4; ++t) {
        const long pbt = pb + (long)t * 4096;
        float4 n0 = ldg4_el(&g4[pbt + fo], pol);
        float4 n1 = ldg4_el(&g4[pbt + fo + 32], pol);
        jb = has_jb ? ldg4_el(&g4[pbt + fo + 64], pol) : z;
        diff4(c0, n0, tv, mse);
        diff4(c1, n1, tv, mse);
        kdiffs(n0, crossk, tv, mse);
        kdiffs(n1, crossk, tv, mse);
        diff4(n0, n1, tv, mse);
        if (has_jb) diff4(n1, jb, tv, mse);
        c0 = n0; c1 = n1;
    }
    // seam plane p0+4 (i-diffs only)
    if (ic < 31) {
        const long pbs = pb + 4L * 4096;
        float4 e0 = ldg4_el(&g4[pbs + fo], pol);
        float4 e1 = ldg4_el(&g4[pbs + fo + 32], pol);
        diff4(c0, e0, tv, mse);
        diff4(c1, e1, tv, mse);
    }

    // block reduce -> 2 atomics into d_out
    #pragma unroll
    for (int off = 16; off > 0; off >>= 1) {
        tv  += __shfl_down_sync(0xffffffffu, tv,  off);
        mse += __shfl_down_sync(0xffffffffu, mse, off);
    }
    __shared__ float stv[8], smse[8];
    if (lane == 0) { stv[jg] = tv; smse[jg] = mse; }
    __syncthreads();
    if (threadIdx.x == 0) {
        float ttv = 0.f, tmse = 0.f;
        #pragma unroll
        for (int w = 0; w < 8; w++) { ttv += stv[w]; tmse += smse[w]; }
        const float tv_norm  = 1.f / (float)(XS * XS * XS);
        const float mse_norm = 1.f / (float)(2 * XS * XS - 2 * XS);
        atomicAdd(&d_out[b],         ttv  * tv_norm);
        atomicAdd(&d_out[BATCH + b], tmse * mse_norm);
    }

    // ---- (plane, strip)-granular zero protocol ----
    // Readers of unit (p, s): owner; j-prev (strip s-1, via jg==7 boundary
    // row); i-prev chunk (seam, only when p % 4 == 0 and p not chunk-first).
    // Sum check per batch: increments = targets = 2168.
    __shared__ int zmask;
    if (threadIdx.x == 0) zmask = 0;
    __syncthreads();                                // all grid reads retired
    if (threadIdx.x == 0) {
        __threadfence();
        int m = 0;
        #pragma unroll
        for (int t = 0; t < 4; ++t) {               // own units
            int tgt = 1 + (s > 0 ? 1 : 0) + ((t == 0 && ic > 0) ? 1 : 0);
            if (atomicAdd(&g_done[(p0 + t) * 8 + s], 1) + 1 == tgt)
                m |= 1 << t;
        }
        if (s < 7) {                                // j-next units we read
            #pragma unroll
            for (int t = 0; t < 4; ++t) {
                int tgt = 2 + ((t == 0 && ic > 0) ? 1 : 0);
                if (atomicAdd(&g_done[(p0 + t) * 8 + s + 1], 1) + 1 == tgt)
                    m |= 1 << (4 + t);
            }
        }
        if (ic < 31) {                              // seam unit we read
            int tgt = 2 + (s > 0 ? 1 : 0);
            if (atomicAdd(&g_done[(p0 + 4) * 8 + s], 1) + 1 == tgt)
                m |= 1 << 8;
        }
        zmask = m;
    }
    __syncthreads();
    int m = zmask;
    #pragma unroll
    for (int t = 0; t < 4; ++t)
        if (m & (1 << t))       zero_unit(p0 + t, s,     threadIdx.x, pol);
    #pragma unroll
    for (int t = 0; t < 4; ++t)
        if (m & (1 << (4 + t))) zero_unit(p0 + t, s + 1, threadIdx.x, pol);
    if (m & (1 << 8))           zero_unit(p0 + 4, s,     threadIdx.x, pol);
}

// ---------------------------------------------------------------------------
extern "C" void kernel_launch(void* const* d_in, const int* in_sizes, int n_in,
                              void* d_out, int out_size) {
    const int*   indices = (const int*)d_in[0];    // (B, M, 3) int32
    const float* values  = (const float*)d_in[1];  // (B, M) float32
    float* out = (float*)d_out;                    // (2, B) float32

    {
        int nthreads = BATCH * TPB_SCAT;            // 500,000
        int threads = 256;
        int blocks = (nthreads + threads - 1) / threads;
        scatter_kernel<<<blocks, threads>>>((const int4*)indices,
                                            (const float4*)values, out);
    }
    {
        reduce_zero_kernel<<<2048, 256>>>(out);
    }
}